// round 1
// baseline (speedup 1.0000x reference)
#include <cuda_runtime.h>
#include <cstdint>
#include <cstddef>

// NeRD pixel decoder, fully fused per image row.
//   Layer 0: implicit 5x5 conv as GEMM  [128 x 3202] @ [3202 x 256]  (tf32 mma)
//   Layers 1,2: [128 x 256] @ [256 x 256]                            (tf32 mma)
//   Head: [128 x 256] @ [256 x 3]                                    (scalar FMA)
// One CTA = one (batch, image-row): M = 128 pixels, N = 256 hidden.

#define FC   128
#define PS   5
#define HID  256
#define OUTC 3
#define IMH  128
#define IMW  128
#define OMEGA 30.0f

#define THREADS 512

#define SMH_STRIDE 260   // 256 + 4 pad -> stride mod 32 == 4 (conflict-free frags)
#define SMA_STRIDE 132   // 128 + 4 halo (2 left, 2 right), also mod 32 == 4
#define SMB_STRIDE 260

#define SMH_FLOATS (128 * SMH_STRIDE)  // 33280
#define SMA_FLOATS (32  * SMA_STRIDE)  // 4224
#define SMB_FLOATS (32  * SMB_STRIDE)  // 8320
#define SMEM_FLOATS (SMH_FLOATS + SMA_FLOATS + SMB_FLOATS)
#define SMEM_BYTES (SMEM_FLOATS * 4)   // 183296 B < 227 KB

__device__ __forceinline__ unsigned f2tf(float f) {
    unsigned u;
    asm("cvt.rna.tf32.f32 %0, %1;" : "=r"(u) : "f"(f));
    return u;
}

// m16n8k8 tf32 mma, fp32 accumulate. Fragment layouts per PTX ISA:
//   A (16x8):  a0:(g,t) a1:(g+8,t) a2:(g,t+4) a3:(g+8,t+4)   g=lane>>2, t=lane&3
//   B (8x8):   b0:(k=t, n=g)  b1:(k=t+4, n=g)
//   C (16x8):  c0:(g,2t) c1:(g,2t+1) c2:(g+8,2t) c3:(g+8,2t+1)
__device__ __forceinline__ void mma8(float* c, const unsigned* a, unsigned b0, unsigned b1) {
    asm("mma.sync.aligned.m16n8k8.row.col.f32.tf32.tf32.f32 "
        "{%0,%1,%2,%3}, {%4,%5,%6,%7}, {%8,%9}, {%0,%1,%2,%3};"
        : "+f"(c[0]), "+f"(c[1]), "+f"(c[2]), "+f"(c[3])
        : "r"(a[0]), "r"(a[1]), "r"(a[2]), "r"(a[3]), "r"(b0), "r"(b1));
}

extern "C" __global__ void __launch_bounds__(THREADS, 1)
nerd_fused_kernel(const float* __restrict__ xi,
                  const float* __restrict__ W0, const float* __restrict__ b0,
                  const float* __restrict__ W1, const float* __restrict__ b1,
                  const float* __restrict__ W2, const float* __restrict__ b2,
                  const float* __restrict__ W3, const float* __restrict__ b3,
                  float* __restrict__ out)
{
    extern __shared__ float smem[];
    float* smH = smem;                     // [128][260] hidden activations (tf32 bits)
    float* smA = smem + SMH_FLOATS;        // [32][132]  xi channel rows (w-halo)
    float* smB = smA + SMA_FLOATS;         // [32][260]  weight k-slab

    const int tid  = threadIdx.x;
    const int lane = tid & 31;
    const int warp = tid >> 5;             // 16 warps
    const int wm   = warp >> 2;            // 0..3  -> m block of 32
    const int wn   = warp & 3;             // 0..3  -> n block of 64
    const int lr   = lane >> 2;            // group id (0..7)
    const int lc   = lane & 3;             // thread-in-group (0..3)

    const int bx   = blockIdx.x;           // 0..255
    const int bimg = bx >> 7;              // batch
    const int hrow = bx & 127;             // image row

    float acc[64];                         // [mt(2)][nt(8)][4]
#pragma unroll
    for (int i = 0; i < 64; ++i) acc[i] = 0.f;

    // ================= Layer 0: implicit conv GEMM =================
    for (int ph = 0; ph < 5; ++ph) {
        const int hh = hrow + ph - 2;
        const bool hok = (hh >= 0) && (hh < IMH);
        for (int cb = 0; cb < 4; ++cb) {           // channel blocks of 32
            __syncthreads();                       // prior consumers of smA/smB done
            // stage A: xi[bimg, cb*32 .. +32, hh, :] with halo, tf32-rounded
            const float* xibase = xi + (((size_t)bimg * FC + cb * 32) * IMH + (hok ? hh : 0)) * IMW;
            for (int idx = tid; idx < 32 * SMA_STRIDE; idx += THREADS) {
                const int c  = idx / SMA_STRIDE;
                const int wa = idx - c * SMA_STRIDE;
                const int w  = wa - 2;
                float v = 0.f;
                if (hok && (unsigned)w < IMW) v = xibase[c * (IMH * IMW) + w];
                smA[c * SMA_STRIDE + wa] = __uint_as_float(f2tf(v));
            }
            for (int pw = 0; pw < 5; ++pw) {
                __syncthreads();                   // previous pw mma done with smB (+A visible)
                // stage B: W0 rows k = (cb*32+ci)*25 + ph*5 + pw
                const int koff = ph * 5 + pw;
                const float* wrow = W0 + (size_t)(cb * 32 * 25 + koff) * HID;
                for (int idx = tid; idx < 32 * HID; idx += THREADS) {
                    const int ci = idx >> 8;
                    const int n  = idx & 255;
                    smB[ci * SMB_STRIDE + n] =
                        __uint_as_float(f2tf(wrow[(size_t)ci * 25 * HID + n]));
                }
                __syncthreads();
#pragma unroll
                for (int kk = 0; kk < 4; ++kk) {
                    const int k0 = kk * 8;
                    unsigned a[2][4];
#pragma unroll
                    for (int mt = 0; mt < 2; ++mt) {
                        const int mbase = wm * 32 + mt * 16 + lr + pw;  // wa = w + pw (halo +2, pw-2)
                        a[mt][0] = __float_as_uint(smA[(k0 + lc)     * SMA_STRIDE + mbase]);
                        a[mt][1] = __float_as_uint(smA[(k0 + lc)     * SMA_STRIDE + mbase + 8]);
                        a[mt][2] = __float_as_uint(smA[(k0 + lc + 4) * SMA_STRIDE + mbase]);
                        a[mt][3] = __float_as_uint(smA[(k0 + lc + 4) * SMA_STRIDE + mbase + 8]);
                    }
#pragma unroll
                    for (int nt = 0; nt < 8; ++nt) {
                        const int n0 = wn * 64 + nt * 8 + lr;
                        const unsigned bb0 = __float_as_uint(smB[(k0 + lc)     * SMB_STRIDE + n0]);
                        const unsigned bb1 = __float_as_uint(smB[(k0 + lc + 4) * SMB_STRIDE + n0]);
                        mma8(&acc[nt * 4],      a[0], bb0, bb1);
                        mma8(&acc[32 + nt * 4], a[1], bb0, bb1);
                    }
                }
            }
        }
    }

    // ---- layer-0 epilogue: + coords*W0[3200:3202] + b0, sin, -> smH ----
    {
        const float gy = -1.f + 2.f * (float)hrow * (1.f / 127.f);
#pragma unroll
        for (int mt = 0; mt < 2; ++mt)
#pragma unroll
            for (int nt = 0; nt < 8; ++nt)
#pragma unroll
                for (int i = 0; i < 4; ++i) {
                    const int m = wm * 32 + mt * 16 + lr + ((i >= 2) ? 8 : 0);
                    const int n = wn * 64 + nt * 8 + lc * 2 + (i & 1);
                    const float gx = -1.f + 2.f * (float)m * (1.f / 127.f);
                    float z = acc[mt * 32 + nt * 4 + i]
                            + gx * W0[3200 * HID + n]
                            + gy * W0[3201 * HID + n]
                            + b0[n];
                    smH[m * SMH_STRIDE + n] = __uint_as_float(f2tf(__sinf(OMEGA * z)));
                }
    }
    __syncthreads();

    // ================= Layers 1 and 2 =================
    for (int L = 0; L < 2; ++L) {
        const float* Wl = L ? W2 : W1;
        const float* bl = L ? b2 : b1;
#pragma unroll
        for (int i = 0; i < 64; ++i) acc[i] = 0.f;
        for (int kb = 0; kb < 8; ++kb) {           // K = 256 in slabs of 32
            __syncthreads();                       // previous slab consumers done
            for (int idx = tid; idx < 32 * HID; idx += THREADS) {
                const int ci = idx >> 8;
                const int n  = idx & 255;
                smB[ci * SMB_STRIDE + n] =
                    __uint_as_float(f2tf(Wl[(size_t)(kb * 32 + ci) * HID + n]));
            }
            __syncthreads();
#pragma unroll
            for (int kk = 0; kk < 4; ++kk) {
                const int k0 = kk * 8;
                const int kg = kb * 32 + k0;
                unsigned a[2][4];
#pragma unroll
                for (int mt = 0; mt < 2; ++mt) {
                    const int mbase = wm * 32 + mt * 16 + lr;
                    a[mt][0] = __float_as_uint(smH[(mbase)     * SMH_STRIDE + kg + lc]);
                    a[mt][1] = __float_as_uint(smH[(mbase + 8) * SMH_STRIDE + kg + lc]);
                    a[mt][2] = __float_as_uint(smH[(mbase)     * SMH_STRIDE + kg + lc + 4]);
                    a[mt][3] = __float_as_uint(smH[(mbase + 8) * SMH_STRIDE + kg + lc + 4]);
                }
#pragma unroll
                for (int nt = 0; nt < 8; ++nt) {
                    const int n0 = wn * 64 + nt * 8 + lr;
                    const unsigned bb0 = __float_as_uint(smB[(k0 + lc)     * SMB_STRIDE + n0]);
                    const unsigned bb1 = __float_as_uint(smB[(k0 + lc + 4) * SMB_STRIDE + n0]);
                    mma8(&acc[nt * 4],      a[0], bb0, bb1);
                    mma8(&acc[32 + nt * 4], a[1], bb0, bb1);
                }
            }
        }
        __syncthreads();                           // all reads of smH done before overwrite
#pragma unroll
        for (int mt = 0; mt < 2; ++mt)
#pragma unroll
            for (int nt = 0; nt < 8; ++nt)
#pragma unroll
                for (int i = 0; i < 4; ++i) {
                    const int m = wm * 32 + mt * 16 + lr + ((i >= 2) ? 8 : 0);
                    const int n = wn * 64 + nt * 8 + lc * 2 + (i & 1);
                    const float z = acc[mt * 32 + nt * 4 + i] + bl[n];
                    smH[m * SMH_STRIDE + n] = __uint_as_float(f2tf(__sinf(OMEGA * z)));
                }
        __syncthreads();
    }

    // ================= Head: [128 x 256] @ [256 x 3] + b3 =================
    for (int idx = tid; idx < IMW * OUTC; idx += THREADS) {
        const int p = idx & 127;        // pixel (w)
        const int o = idx >> 7;         // output channel
        float sum = b3[o];
#pragma unroll 8
        for (int k = 0; k < HID; ++k)
            sum += smH[p * SMH_STRIDE + k] * W3[k * OUTC + o];
        out[(((size_t)bimg * OUTC + o) * IMH + hrow) * IMW + p] = sum;
    }
}

extern "C" void kernel_launch(void* const* d_in, const int* in_sizes, int n_in,
                              void* d_out, int out_size)
{
    const float* xi = (const float*)d_in[0];
    const float* W0 = (const float*)d_in[1];
    const float* b0 = (const float*)d_in[2];
    const float* W1 = (const float*)d_in[3];
    const float* b1 = (const float*)d_in[4];
    const float* W2 = (const float*)d_in[5];
    const float* b2 = (const float*)d_in[6];
    const float* W3 = (const float*)d_in[7];
    const float* b3 = (const float*)d_in[8];
    float* out = (float*)d_out;

    cudaFuncSetAttribute(nerd_fused_kernel,
                         cudaFuncAttributeMaxDynamicSharedMemorySize, SMEM_BYTES);

    nerd_fused_kernel<<<256, THREADS, SMEM_BYTES>>>(
        xi, W0, b0, W1, b1, W2, b2, W3, b3, out);
}

// round 2
// speedup vs baseline: 1.0009x; 1.0009x over previous
#include <cuda_runtime.h>
#include <cstdint>
#include <cstddef>

// NeRD pixel decoder, fully fused per image row.
//   Layer 0: implicit 5x5 conv as GEMM  [128 x 3202] @ [3202 x 256]  (tf32 mma)
//   Layers 1,2: [128 x 256] @ [256 x 256]                            (tf32 mma)
//   Head: [128 x 256] @ [256 x 3]                                    (scalar FMA)
// One CTA = one (batch, image-row): M = 128 pixels, N = 256 hidden.

#define FC   128
#define PS   5
#define HID  256
#define OUTC 3
#define IMH  128
#define IMW  128
#define OMEGA 30.0f

#define THREADS 512

#define SMH_STRIDE 260   // 256 + 4 pad -> stride mod 32 == 4 (conflict-free frags)
#define SMA_STRIDE 132   // 128 + 4 halo (2 left, 2 right), also mod 32 == 4
#define SMB_STRIDE 260

#define SMH_FLOATS (128 * SMH_STRIDE)  // 33280
#define SMA_FLOATS (32  * SMA_STRIDE)  // 4224
#define SMB_FLOATS (32  * SMB_STRIDE)  // 8320
#define SMEM_FLOATS (SMH_FLOATS + SMA_FLOATS + SMB_FLOATS)
#define SMEM_BYTES (SMEM_FLOATS * 4)   // 183296 B < 227 KB

__device__ __forceinline__ unsigned f2tf(float f) {
    unsigned u;
    asm("cvt.rna.tf32.f32 %0, %1;" : "=r"(u) : "f"(f));
    return u;
}

// m16n8k8 tf32 mma, fp32 accumulate. Fragment layouts per PTX ISA:
//   A (16x8):  a0:(g,t) a1:(g+8,t) a2:(g,t+4) a3:(g+8,t+4)   g=lane>>2, t=lane&3
//   B (8x8):   b0:(k=t, n=g)  b1:(k=t+4, n=g)
//   C (16x8):  c0:(g,2t) c1:(g,2t+1) c2:(g+8,2t) c3:(g+8,2t+1)
__device__ __forceinline__ void mma8(float* c, const unsigned* a, unsigned b0, unsigned b1) {
    asm("mma.sync.aligned.m16n8k8.row.col.f32.tf32.tf32.f32 "
        "{%0,%1,%2,%3}, {%4,%5,%6,%7}, {%8,%9}, {%0,%1,%2,%3};"
        : "+f"(c[0]), "+f"(c[1]), "+f"(c[2]), "+f"(c[3])
        : "r"(a[0]), "r"(a[1]), "r"(a[2]), "r"(a[3]), "r"(b0), "r"(b1));
}

extern "C" __global__ void __launch_bounds__(THREADS, 1)
nerd_fused_kernel(const float* __restrict__ xi,
                  const float* __restrict__ W0, const float* __restrict__ b0,
                  const float* __restrict__ W1, const float* __restrict__ b1,
                  const float* __restrict__ W2, const float* __restrict__ b2,
                  const float* __restrict__ W3, const float* __restrict__ b3,
                  float* __restrict__ out)
{
    extern __shared__ float smem[];
    float* smH = smem;                     // [128][260] hidden activations (tf32 bits)
    float* smA = smem + SMH_FLOATS;        // [32][132]  xi channel rows (w-halo)
    float* smB = smA + SMA_FLOATS;         // [32][260]  weight k-slab

    const int tid  = threadIdx.x;
    const int lane = tid & 31;
    const int warp = tid >> 5;             // 16 warps
    const int wm   = warp >> 2;            // 0..3  -> m block of 32
    const int wn   = warp & 3;             // 0..3  -> n block of 64
    const int lr   = lane >> 2;            // group id (0..7)
    const int lc   = lane & 3;             // thread-in-group (0..3)

    const int bx   = blockIdx.x;           // 0..255
    const int bimg = bx >> 7;              // batch
    const int hrow = bx & 127;             // image row

    float acc[64];                         // [mt(2)][nt(8)][4]
#pragma unroll
    for (int i = 0; i < 64; ++i) acc[i] = 0.f;

    // ================= Layer 0: implicit conv GEMM =================
    for (int ph = 0; ph < 5; ++ph) {
        const int hh = hrow + ph - 2;
        const bool hok = (hh >= 0) && (hh < IMH);
        for (int cb = 0; cb < 4; ++cb) {           // channel blocks of 32
            __syncthreads();                       // prior consumers of smA/smB done
            // stage A: xi[bimg, cb*32 .. +32, hh, :] with halo, tf32-rounded
            const float* xibase = xi + (((size_t)bimg * FC + cb * 32) * IMH + (hok ? hh : 0)) * IMW;
            for (int idx = tid; idx < 32 * SMA_STRIDE; idx += THREADS) {
                const int c  = idx / SMA_STRIDE;
                const int wa = idx - c * SMA_STRIDE;
                const int w  = wa - 2;
                float v = 0.f;
                if (hok && (unsigned)w < IMW) v = xibase[c * (IMH * IMW) + w];
                smA[c * SMA_STRIDE + wa] = __uint_as_float(f2tf(v));
            }
            for (int pw = 0; pw < 5; ++pw) {
                __syncthreads();                   // previous pw mma done with smB (+A visible)
                // stage B: W0 rows k = (cb*32+ci)*25 + ph*5 + pw
                const int koff = ph * 5 + pw;
                const float* wrow = W0 + (size_t)(cb * 32 * 25 + koff) * HID;
                for (int idx = tid; idx < 32 * HID; idx += THREADS) {
                    const int ci = idx >> 8;
                    const int n  = idx & 255;
                    smB[ci * SMB_STRIDE + n] =
                        __uint_as_float(f2tf(wrow[(size_t)ci * 25 * HID + n]));
                }
                __syncthreads();
#pragma unroll
                for (int kk = 0; kk < 4; ++kk) {
                    const int k0 = kk * 8;
                    unsigned a[2][4];
#pragma unroll
                    for (int mt = 0; mt < 2; ++mt) {
                        const int mbase = wm * 32 + mt * 16 + lr + pw;  // wa = w + pw (halo +2, pw-2)
                        a[mt][0] = __float_as_uint(smA[(k0 + lc)     * SMA_STRIDE + mbase]);
                        a[mt][1] = __float_as_uint(smA[(k0 + lc)     * SMA_STRIDE + mbase + 8]);
                        a[mt][2] = __float_as_uint(smA[(k0 + lc + 4) * SMA_STRIDE + mbase]);
                        a[mt][3] = __float_as_uint(smA[(k0 + lc + 4) * SMA_STRIDE + mbase + 8]);
                    }
#pragma unroll
                    for (int nt = 0; nt < 8; ++nt) {
                        const int n0 = wn * 64 + nt * 8 + lr;
                        const unsigned bb0 = __float_as_uint(smB[(k0 + lc)     * SMB_STRIDE + n0]);
                        const unsigned bb1 = __float_as_uint(smB[(k0 + lc + 4) * SMB_STRIDE + n0]);
                        mma8(&acc[nt * 4],      a[0], bb0, bb1);
                        mma8(&acc[32 + nt * 4], a[1], bb0, bb1);
                    }
                }
            }
        }
    }

    // ---- layer-0 epilogue: + coords*W0[3200:3202] + b0, sin, -> smH ----
    {
        const float gy = -1.f + 2.f * (float)hrow * (1.f / 127.f);
#pragma unroll
        for (int mt = 0; mt < 2; ++mt)
#pragma unroll
            for (int nt = 0; nt < 8; ++nt)
#pragma unroll
                for (int i = 0; i < 4; ++i) {
                    const int m = wm * 32 + mt * 16 + lr + ((i >= 2) ? 8 : 0);
                    const int n = wn * 64 + nt * 8 + lc * 2 + (i & 1);
                    const float gx = -1.f + 2.f * (float)m * (1.f / 127.f);
                    float z = acc[mt * 32 + nt * 4 + i]
                            + gx * W0[3200 * HID + n]
                            + gy * W0[3201 * HID + n]
                            + b0[n];
                    smH[m * SMH_STRIDE + n] = __uint_as_float(f2tf(__sinf(OMEGA * z)));
                }
    }
    __syncthreads();

    // ================= Layers 1 and 2 =================
    for (int L = 0; L < 2; ++L) {
        const float* Wl = L ? W2 : W1;
        const float* bl = L ? b2 : b1;
#pragma unroll
        for (int i = 0; i < 64; ++i) acc[i] = 0.f;
        for (int kb = 0; kb < 8; ++kb) {           // K = 256 in slabs of 32
            __syncthreads();                       // previous slab consumers done
            for (int idx = tid; idx < 32 * HID; idx += THREADS) {
                const int ci = idx >> 8;
                const int n  = idx & 255;
                smB[ci * SMB_STRIDE + n] =
                    __uint_as_float(f2tf(Wl[(size_t)(kb * 32 + ci) * HID + n]));
            }
            __syncthreads();
#pragma unroll
            for (int kk = 0; kk < 4; ++kk) {
                const int k0 = kk * 8;
                const int kg = kb * 32 + k0;
                unsigned a[2][4];
#pragma unroll
                for (int mt = 0; mt < 2; ++mt) {
                    const int mbase = wm * 32 + mt * 16 + lr;
                    a[mt][0] = __float_as_uint(smH[(mbase)     * SMH_STRIDE + kg + lc]);
                    a[mt][1] = __float_as_uint(smH[(mbase + 8) * SMH_STRIDE + kg + lc]);
                    a[mt][2] = __float_as_uint(smH[(mbase)     * SMH_STRIDE + kg + lc + 4]);
                    a[mt][3] = __float_as_uint(smH[(mbase + 8) * SMH_STRIDE + kg + lc + 4]);
                }
#pragma unroll
                for (int nt = 0; nt < 8; ++nt) {
                    const int n0 = wn * 64 + nt * 8 + lr;
                    const unsigned bb0 = __float_as_uint(smB[(k0 + lc)     * SMB_STRIDE + n0]);
                    const unsigned bb1 = __float_as_uint(smB[(k0 + lc + 4) * SMB_STRIDE + n0]);
                    mma8(&acc[nt * 4],      a[0], bb0, bb1);
                    mma8(&acc[32 + nt * 4], a[1], bb0, bb1);
                }
            }
        }
        __syncthreads();                           // all reads of smH done before overwrite
#pragma unroll
        for (int mt = 0; mt < 2; ++mt)
#pragma unroll
            for (int nt = 0; nt < 8; ++nt)
#pragma unroll
                for (int i = 0; i < 4; ++i) {
                    const int m = wm * 32 + mt * 16 + lr + ((i >= 2) ? 8 : 0);
                    const int n = wn * 64 + nt * 8 + lc * 2 + (i & 1);
                    const float z = acc[mt * 32 + nt * 4 + i] + bl[n];
                    smH[m * SMH_STRIDE + n] = __uint_as_float(f2tf(__sinf(OMEGA * z)));
                }
        __syncthreads();
    }

    // ================= Head: [128 x 256] @ [256 x 3] + b3 =================
    for (int idx = tid; idx < IMW * OUTC; idx += THREADS) {
        const int p = idx & 127;        // pixel (w)
        const int o = idx >> 7;         // output channel
        float sum = b3[o];
#pragma unroll 8
        for (int k = 0; k < HID; ++k)
            sum += smH[p * SMH_STRIDE + k] * W3[k * OUTC + o];
        out[(((size_t)bimg * OUTC + o) * IMH + hrow) * IMW + p] = sum;
    }
}

extern "C" void kernel_launch(void* const* d_in, const int* in_sizes, int n_in,
                              void* d_out, int out_size)
{
    const float* xi = (const float*)d_in[0];
    const float* W0 = (const float*)d_in[1];
    const float* b0 = (const float*)d_in[2];
    const float* W1 = (const float*)d_in[3];
    const float* b1 = (const float*)d_in[4];
    const float* W2 = (const float*)d_in[5];
    const float* b2 = (const float*)d_in[6];
    const float* W3 = (const float*)d_in[7];
    const float* b3 = (const float*)d_in[8];
    float* out = (float*)d_out;

    cudaFuncSetAttribute(nerd_fused_kernel,
                         cudaFuncAttributeMaxDynamicSharedMemorySize, SMEM_BYTES);

    nerd_fused_kernel<<<256, THREADS, SMEM_BYTES>>>(
        xi, W0, b0, W1, b1, W2, b2, W3, b3, out);
}

// round 3
// speedup vs baseline: 1.5928x; 1.5914x over previous
#include <cuda_runtime.h>
#include <cstdint>
#include <cstddef>

// NeRD pixel decoder, fully fused per image row.
//   Layer 0: implicit 5x5 conv as GEMM  [128 x 3202] @ [3202 x 256]  (tf32 mma)
//   Layers 1,2: [128 x 256] @ [256 x 256]                            (tf32 mma)
//   Head: [128 x 256] @ [256 x 3]                                    (scalar FMA)
// One CTA = one (batch, image-row): M = 128 pixels, N = 256 hidden.
//
// Bank-conflict rules derived in R2:
//   k-major operand (A/B slabs, k in rows):  frag addr = lc*stride + lr
//       -> need stride % 32 == 8  (bank = 8*lc + lr, all 32 distinct)
//   m-major operand (smH, m in rows):        frag addr = lr*stride + lc
//       -> need stride % 32 == 4  (bank = 4*lr + lc, all 32 distinct)

#define FC   128
#define PS   5
#define HID  256
#define OUTC 3
#define IMH  128
#define IMW  128
#define OMEGA 30.0f

#define THREADS 512

#define SMH_STRIDE 260   // 256 + 4 : m-major operand, stride%32==4 -> conflict-free
#define SMA_STRIDE 136   // 128 + 4 halo + 4 pad : k-major, stride%32==8 -> conflict-free
#define SMB_STRIDE 264   // 256 + 8 : k-major, stride%32==8 -> conflict-free

#define SMH_FLOATS (128 * SMH_STRIDE)  // 33280
#define SMA_FLOATS (32  * SMA_STRIDE)  // 4352
#define SMB_FLOATS (32  * SMB_STRIDE)  // 8448
#define SMEM_FLOATS (SMH_FLOATS + SMA_FLOATS + SMB_FLOATS)
#define SMEM_BYTES (SMEM_FLOATS * 4)   // 184320 B < 227 KB

__device__ __forceinline__ unsigned f2tf(float f) {
    unsigned u;
    asm("cvt.rna.tf32.f32 %0, %1;" : "=r"(u) : "f"(f));
    return u;
}

__device__ __forceinline__ float4 f2tf4(float4 v) {
    float4 t;
    t.x = __uint_as_float(f2tf(v.x));
    t.y = __uint_as_float(f2tf(v.y));
    t.z = __uint_as_float(f2tf(v.z));
    t.w = __uint_as_float(f2tf(v.w));
    return t;
}

// m16n8k8 tf32 mma, fp32 accumulate. Fragment layouts per PTX ISA:
//   A (16x8):  a0:(g,t) a1:(g+8,t) a2:(g,t+4) a3:(g+8,t+4)   g=lane>>2, t=lane&3
//   B (8x8):   b0:(k=t, n=g)  b1:(k=t+4, n=g)
//   C (16x8):  c0:(g,2t) c1:(g,2t+1) c2:(g+8,2t) c3:(g+8,2t+1)
__device__ __forceinline__ void mma8(float* c, const unsigned* a, unsigned b0, unsigned b1) {
    asm("mma.sync.aligned.m16n8k8.row.col.f32.tf32.tf32.f32 "
        "{%0,%1,%2,%3}, {%4,%5,%6,%7}, {%8,%9}, {%0,%1,%2,%3};"
        : "+f"(c[0]), "+f"(c[1]), "+f"(c[2]), "+f"(c[3])
        : "r"(a[0]), "r"(a[1]), "r"(a[2]), "r"(a[3]), "r"(b0), "r"(b1));
}

extern "C" __global__ void __launch_bounds__(THREADS, 1)
nerd_fused_kernel(const float* __restrict__ xi,
                  const float* __restrict__ W0, const float* __restrict__ b0,
                  const float* __restrict__ W1, const float* __restrict__ b1,
                  const float* __restrict__ W2, const float* __restrict__ b2,
                  const float* __restrict__ W3, const float* __restrict__ b3,
                  float* __restrict__ out)
{
    extern __shared__ float smem[];
    float* smH = smem;                     // [128][260] hidden activations (tf32 bits)
    float* smA = smem + SMH_FLOATS;        // [32][136]  xi channel rows (w-halo)
    float* smB = smA + SMA_FLOATS;         // [32][264]  weight k-slab

    const int tid  = threadIdx.x;
    const int lane = tid & 31;
    const int warp = tid >> 5;             // 16 warps
    const int wm   = warp >> 2;            // 0..3  -> m block of 32
    const int wn   = warp & 3;             // 0..3  -> n block of 64
    const int lr   = lane >> 2;            // group id (0..7)
    const int lc   = lane & 3;             // thread-in-group (0..3)

    const int bx   = blockIdx.x;           // 0..255
    const int bimg = bx >> 7;              // batch
    const int hrow = bx & 127;             // image row

    float acc[64];                         // [mt(2)][nt(8)][4]
#pragma unroll
    for (int i = 0; i < 64; ++i) acc[i] = 0.f;

    // ================= Layer 0: implicit conv GEMM =================
    for (int ph = 0; ph < 5; ++ph) {
        const int hh = hrow + ph - 2;
        const bool hok = (hh >= 0) && (hh < IMH);
        for (int cb = 0; cb < 4; ++cb) {           // channel blocks of 32
            __syncthreads();                       // prior consumers of smA/smB done
            // stage A: xi[bimg, cb*32 .. +32, hh, :] with halo, tf32-rounded
            const float* xibase = xi + (((size_t)bimg * FC + cb * 32) * IMH + (hok ? hh : 0)) * IMW;
            for (int idx = tid; idx < 32 * SMA_STRIDE; idx += THREADS) {
                const int c  = idx / SMA_STRIDE;
                const int wa = idx - c * SMA_STRIDE;
                const int w  = wa - 2;
                float v = 0.f;
                if (hok && (unsigned)w < IMW) v = xibase[c * (IMH * IMW) + w];
                smA[c * SMA_STRIDE + wa] = __uint_as_float(f2tf(v));
            }
            for (int pw = 0; pw < 5; ++pw) {
                __syncthreads();                   // previous pw mma done with smB (+A visible)
                // stage B (float4): W0 rows k = (cb*32+ci)*25 + ph*5 + pw
                const int koff = ph * 5 + pw;
                const float* wrow = W0 + (size_t)(cb * 32 * 25 + koff) * HID;
#pragma unroll
                for (int f = tid; f < 32 * 64; f += THREADS) {   // 2048 float4
                    const int ci = f >> 6;
                    const int n4 = (f & 63) << 2;
                    float4 v = *reinterpret_cast<const float4*>(
                        wrow + (size_t)ci * 25 * HID + n4);
                    *reinterpret_cast<float4*>(smB + ci * SMB_STRIDE + n4) = f2tf4(v);
                }
                __syncthreads();
#pragma unroll
                for (int kk = 0; kk < 4; ++kk) {
                    const int k0 = kk * 8;
                    unsigned a[2][4];
#pragma unroll
                    for (int mt = 0; mt < 2; ++mt) {
                        const int mbase = wm * 32 + mt * 16 + lr + pw;  // wa = w + pw (halo +2, pw-2)
                        a[mt][0] = __float_as_uint(smA[(k0 + lc)     * SMA_STRIDE + mbase]);
                        a[mt][1] = __float_as_uint(smA[(k0 + lc)     * SMA_STRIDE + mbase + 8]);
                        a[mt][2] = __float_as_uint(smA[(k0 + lc + 4) * SMA_STRIDE + mbase]);
                        a[mt][3] = __float_as_uint(smA[(k0 + lc + 4) * SMA_STRIDE + mbase + 8]);
                    }
#pragma unroll
                    for (int nt = 0; nt < 8; ++nt) {
                        const int n0 = wn * 64 + nt * 8 + lr;
                        const unsigned bb0 = __float_as_uint(smB[(k0 + lc)     * SMB_STRIDE + n0]);
                        const unsigned bb1 = __float_as_uint(smB[(k0 + lc + 4) * SMB_STRIDE + n0]);
                        mma8(&acc[nt * 4],      a[0], bb0, bb1);
                        mma8(&acc[32 + nt * 4], a[1], bb0, bb1);
                    }
                }
            }
        }
    }

    // ---- layer-0 epilogue: + coords*W0[3200:3202] + b0, sin, -> smH ----
    {
        const float gy = -1.f + 2.f * (float)hrow * (1.f / 127.f);
#pragma unroll
        for (int mt = 0; mt < 2; ++mt)
#pragma unroll
            for (int nt = 0; nt < 8; ++nt)
#pragma unroll
                for (int i = 0; i < 4; ++i) {
                    const int m = wm * 32 + mt * 16 + lr + ((i >= 2) ? 8 : 0);
                    const int n = wn * 64 + nt * 8 + lc * 2 + (i & 1);
                    const float gx = -1.f + 2.f * (float)m * (1.f / 127.f);
                    float z = acc[mt * 32 + nt * 4 + i]
                            + gx * W0[3200 * HID + n]
                            + gy * W0[3201 * HID + n]
                            + b0[n];
                    smH[m * SMH_STRIDE + n] = __uint_as_float(f2tf(__sinf(OMEGA * z)));
                }
    }
    __syncthreads();

    // ================= Layers 1 and 2 =================
    for (int L = 0; L < 2; ++L) {
        const float* Wl = L ? W2 : W1;
        const float* bl = L ? b2 : b1;
#pragma unroll
        for (int i = 0; i < 64; ++i) acc[i] = 0.f;
        for (int kb = 0; kb < 8; ++kb) {           // K = 256 in slabs of 32
            __syncthreads();                       // previous slab consumers done
            const float* wb = Wl + (size_t)kb * 32 * HID;
#pragma unroll
            for (int f = tid; f < 32 * 64; f += THREADS) {   // 2048 float4
                const int ci = f >> 6;
                const int n4 = (f & 63) << 2;
                float4 v = *reinterpret_cast<const float4*>(wb + (size_t)ci * HID + n4);
                *reinterpret_cast<float4*>(smB + ci * SMB_STRIDE + n4) = f2tf4(v);
            }
            __syncthreads();
#pragma unroll
            for (int kk = 0; kk < 4; ++kk) {
                const int k0 = kk * 8;
                const int kg = kb * 32 + k0;
                unsigned a[2][4];
#pragma unroll
                for (int mt = 0; mt < 2; ++mt) {
                    const int mbase = wm * 32 + mt * 16 + lr;
                    a[mt][0] = __float_as_uint(smH[(mbase)     * SMH_STRIDE + kg + lc]);
                    a[mt][1] = __float_as_uint(smH[(mbase + 8) * SMH_STRIDE + kg + lc]);
                    a[mt][2] = __float_as_uint(smH[(mbase)     * SMH_STRIDE + kg + lc + 4]);
                    a[mt][3] = __float_as_uint(smH[(mbase + 8) * SMH_STRIDE + kg + lc + 4]);
                }
#pragma unroll
                for (int nt = 0; nt < 8; ++nt) {
                    const int n0 = wn * 64 + nt * 8 + lr;
                    const unsigned bb0 = __float_as_uint(smB[(k0 + lc)     * SMB_STRIDE + n0]);
                    const unsigned bb1 = __float_as_uint(smB[(k0 + lc + 4) * SMB_STRIDE + n0]);
                    mma8(&acc[nt * 4],      a[0], bb0, bb1);
                    mma8(&acc[32 + nt * 4], a[1], bb0, bb1);
                }
            }
        }
        __syncthreads();                           // all reads of smH done before overwrite
#pragma unroll
        for (int mt = 0; mt < 2; ++mt)
#pragma unroll
            for (int nt = 0; nt < 8; ++nt)
#pragma unroll
                for (int i = 0; i < 4; ++i) {
                    const int m = wm * 32 + mt * 16 + lr + ((i >= 2) ? 8 : 0);
                    const int n = wn * 64 + nt * 8 + lc * 2 + (i & 1);
                    const float z = acc[mt * 32 + nt * 4 + i] + bl[n];
                    smH[m * SMH_STRIDE + n] = __uint_as_float(f2tf(__sinf(OMEGA * z)));
                }
        __syncthreads();
    }

    // ================= Head: [128 x 256] @ [256 x 3] + b3 =================
    for (int idx = tid; idx < IMW * OUTC; idx += THREADS) {
        const int p = idx & 127;        // pixel (w)
        const int o = idx >> 7;         // output channel
        float sum = b3[o];
#pragma unroll 8
        for (int k = 0; k < HID; ++k)
            sum += smH[p * SMH_STRIDE + k] * W3[k * OUTC + o];
        out[(((size_t)bimg * OUTC + o) * IMH + hrow) * IMW + p] = sum;
    }
}

extern "C" void kernel_launch(void* const* d_in, const int* in_sizes, int n_in,
                              void* d_out, int out_size)
{
    const float* xi = (const float*)d_in[0];
    const float* W0 = (const float*)d_in[1];
    const float* b0 = (const float*)d_in[2];
    const float* W1 = (const float*)d_in[3];
    const float* b1 = (const float*)d_in[4];
    const float* W2 = (const float*)d_in[5];
    const float* b2 = (const float*)d_in[6];
    const float* W3 = (const float*)d_in[7];
    const float* b3 = (const float*)d_in[8];
    float* out = (float*)d_out;

    cudaFuncSetAttribute(nerd_fused_kernel,
                         cudaFuncAttributeMaxDynamicSharedMemorySize, SMEM_BYTES);

    nerd_fused_kernel<<<256, THREADS, SMEM_BYTES>>>(
        xi, W0, b0, W1, b1, W2, b2, W3, b3, out);
}